// round 16
// baseline (speedup 1.0000x reference)
#include <cuda_runtime.h>
#include <cuda_bf16.h>
#include <math.h>
#include <cstdint>

#define NN 50000
#define NE 400000

// =============== mma.sync helpers ===============
__device__ __forceinline__ uint32_t smem_to_u32(const void* p) {
    uint32_t a;
    asm("{ .reg .u64 t; cvta.to.shared.u64 t, %1; cvt.u32.u64 %0, t; }" : "=r"(a) : "l"(p));
    return a;
}
__device__ __forceinline__ void ldsm_x4(uint32_t addr, uint32_t* r) {
    asm volatile("ldmatrix.sync.aligned.m8n8.x4.shared.b16 {%0,%1,%2,%3}, [%4];"
        : "=r"(r[0]), "=r"(r[1]), "=r"(r[2]), "=r"(r[3]) : "r"(addr));
}
__device__ __forceinline__ void mma_bf16(float* d, const uint32_t* a, const uint32_t* b) {
    asm volatile("mma.sync.aligned.m16n8k16.row.col.f32.bf16.bf16.f32 "
        "{%0,%1,%2,%3}, {%4,%5,%6,%7}, {%8,%9}, {%0,%1,%2,%3};"
        : "+f"(d[0]), "+f"(d[1]), "+f"(d[2]), "+f"(d[3])
        : "r"(a[0]), "r"(a[1]), "r"(a[2]), "r"(a[3]), "r"(b[0]), "r"(b[1]));
}
__device__ __forceinline__ uint32_t a_lane_addr(uint32_t base, int R, int lane, int stride) {
    int t = lane >> 3;
    int row = R + (lane & 7) + (t & 1) * 8;
    int k8  = (t >> 1) * 8;
    return base + row * stride + k8 * 2;
}
__device__ __forceinline__ uint32_t b_lane_addr(uint32_t base, int lane, int stride) {
    int t = lane >> 3;
    int n  = (lane & 7) + (t >> 1) * 8;
    int k8 = (t & 1) * 8;
    return base + n * stride + k8 * 2;
}
// half-width N=64 (4 n-pairs), M16, acc[8][4]  (edge_logits)
template<int KSTEPS>
__device__ __forceinline__ void warp_gemm_h(
    uint32_t aH, uint32_t aL, uint32_t bH, uint32_t bL, int bstride, float (*acc)[4])
{
#pragma unroll
    for (int ks = 0; ks < KSTEPS; ks++) {
        uint32_t rah[4], ral[4];
        ldsm_x4(aH + ks * 32, rah);
        ldsm_x4(aL + ks * 32, ral);
#pragma unroll
        for (int nbp = 0; nbp < 4; nbp++) {
            uint32_t bh[4], bl[4];
            ldsm_x4(bH + nbp * 16 * bstride + ks * 32, bh);
            ldsm_x4(bL + nbp * 16 * bstride + ks * 32, bl);
            mma_bf16(acc[2 * nbp],     rah, bh);
            mma_bf16(acc[2 * nbp],     rah, bl);
            mma_bf16(acc[2 * nbp],     ral, bh);
            mma_bf16(acc[2 * nbp + 1], rah, bh + 2);
            mma_bf16(acc[2 * nbp + 1], rah, bl + 2);
            mma_bf16(acc[2 * nbp + 1], ral, bh + 2);
        }
    }
}
// node phase 1: single B image, both A parts, 2 M-tiles -> acc += (aH+aL)·B
template<int KSTEPS>
__device__ __forceinline__ void warp_gemm_bh(
    uint32_t aH, uint32_t aL, int astride,
    uint32_t bB, int bstride,
    float (*acc0)[4], float (*acc1)[4])
{
#pragma unroll
    for (int ks = 0; ks < KSTEPS; ks++) {
        uint32_t rah0[4], ral0[4], rah1[4], ral1[4];
        ldsm_x4(aH + ks * 32, rah0);
        ldsm_x4(aL + ks * 32, ral0);
        ldsm_x4(aH + 16 * astride + ks * 32, rah1);
        ldsm_x4(aL + 16 * astride + ks * 32, ral1);
#pragma unroll
        for (int nbp = 0; nbp < 4; nbp++) {
            uint32_t bb[4];
            ldsm_x4(bB + nbp * 16 * bstride + ks * 32, bb);
            mma_bf16(acc0[2 * nbp],     rah0, bb);
            mma_bf16(acc0[2 * nbp],     ral0, bb);
            mma_bf16(acc0[2 * nbp + 1], rah0, bb + 2);
            mma_bf16(acc0[2 * nbp + 1], ral0, bb + 2);
            mma_bf16(acc1[2 * nbp],     rah1, bb);
            mma_bf16(acc1[2 * nbp],     ral1, bb);
            mma_bf16(acc1[2 * nbp + 1], rah1, bb + 2);
            mma_bf16(acc1[2 * nbp + 1], ral1, bb + 2);
        }
    }
}
// node phase 2: single B image, A_hi only, 2 M-tiles -> acc += aH·B
template<int KSTEPS>
__device__ __forceinline__ void warp_gemm_al(
    uint32_t aH, int astride,
    uint32_t bB, int bstride,
    float (*acc0)[4], float (*acc1)[4])
{
#pragma unroll
    for (int ks = 0; ks < KSTEPS; ks++) {
        uint32_t rah0[4], rah1[4];
        ldsm_x4(aH + ks * 32, rah0);
        ldsm_x4(aH + 16 * astride + ks * 32, rah1);
#pragma unroll
        for (int nbp = 0; nbp < 4; nbp++) {
            uint32_t bb[4];
            ldsm_x4(bB + nbp * 16 * bstride + ks * 32, bb);
            mma_bf16(acc0[2 * nbp],     rah0, bb);
            mma_bf16(acc0[2 * nbp + 1], rah0, bb + 2);
            mma_bf16(acc1[2 * nbp],     rah1, bb);
            mma_bf16(acc1[2 * nbp + 1], rah1, bb + 2);
        }
    }
}
// M32 x N64 paired-B (wc P-GEMMs)
template<int KSTEPS>
__device__ __forceinline__ void warp_gemm_m2(
    uint32_t aH, uint32_t aL, int astride,
    uint32_t bH, uint32_t bL, int bstride,
    float (*acc0)[4], float (*acc1)[4])
{
#pragma unroll
    for (int ks = 0; ks < KSTEPS; ks++) {
        uint32_t rah0[4], ral0[4], rah1[4], ral1[4];
        ldsm_x4(aH + ks * 32, rah0);
        ldsm_x4(aL + ks * 32, ral0);
        ldsm_x4(aH + 16 * astride + ks * 32, rah1);
        ldsm_x4(aL + 16 * astride + ks * 32, ral1);
#pragma unroll
        for (int nbp = 0; nbp < 4; nbp++) {
            uint32_t bh[4], bl[4];
            ldsm_x4(bH + nbp * 16 * bstride + ks * 32, bh);
            ldsm_x4(bL + nbp * 16 * bstride + ks * 32, bl);
            mma_bf16(acc0[2 * nbp],     rah0, bh);
            mma_bf16(acc0[2 * nbp],     rah0, bl);
            mma_bf16(acc0[2 * nbp],     ral0, bh);
            mma_bf16(acc0[2 * nbp + 1], rah0, bh + 2);
            mma_bf16(acc0[2 * nbp + 1], rah0, bl + 2);
            mma_bf16(acc0[2 * nbp + 1], ral0, bh + 2);
            mma_bf16(acc1[2 * nbp],     rah1, bh);
            mma_bf16(acc1[2 * nbp],     rah1, bl);
            mma_bf16(acc1[2 * nbp],     ral1, bh);
            mma_bf16(acc1[2 * nbp + 1], rah1, bh + 2);
            mma_bf16(acc1[2 * nbp + 1], rah1, bl + 2);
            mma_bf16(acc1[2 * nbp + 1], ral1, bh + 2);
        }
    }
}

__device__ __forceinline__ float silu_f(float x) { return x / (1.0f + __expf(-x)); }
__device__ __forceinline__ void split2(float x0, float x1, uint32_t& hi, uint32_t& lo) {
    __nv_bfloat16 h0 = __float2bfloat16(x0), h1 = __float2bfloat16(x1);
    __nv_bfloat16 l0 = __float2bfloat16(x0 - __bfloat162float(h0));
    __nv_bfloat16 l1 = __float2bfloat16(x1 - __bfloat162float(h1));
    __nv_bfloat162 H; H.x = h0; H.y = h1;
    __nv_bfloat162 L; L.x = l0; L.y = l1;
    hi = *(uint32_t*)&H; lo = *(uint32_t*)&L;
}

// =============== scratch globals ===============
__device__ __align__(16) float g_q [NN * 128];
__device__ __align__(16) float g_k [NN * 128];
__device__ __align__(16) float g_P [(size_t)NN * 1024];
__device__ __align__(16) float g_a [(size_t)NE * 8];
__device__ int g_cnt  [NN];
__device__ int g_cntI [NN];
__device__ int g_off  [NN + 1];
__device__ int g_offI [NN + 1];
__device__ int g_order [NE];
__device__ int g_orderI[NE];
#define SCH 512
#define SNB ((NN + SCH - 1) / SCH)
__device__ int g_part[2][SNB];
__device__ int g_pp  [2][SNB];
__device__ __align__(16) __nv_bfloat16 g_wimg [4][2][128 * 136];
__device__ __align__(16) __nv_bfloat16 g_wreimg[2][128 * 72];
__device__ __align__(16) __nv_bfloat16 g_wcimg [8][2][128 * 24];

// =============== merged weight prep ===============
__global__ void prep_all(const float* __restrict__ wq, const float* __restrict__ wk,
                         const float* __restrict__ mw1, const float* __restrict__ mw2,
                         const float* __restrict__ wre, const float* __restrict__ wc) {
    int gid = blockIdx.x * blockDim.x + threadIdx.x;
    if (gid < 65536) {
        int m = gid >> 14, idx = gid & 16383;
        const float* W = (m == 0) ? wq : (m == 1) ? wk : (m == 2) ? mw1 : mw2;
        int k = idx >> 7, n = idx & 127;
        float w = W[k * 128 + n];
        __nv_bfloat16 h = __float2bfloat16(w);
        __nv_bfloat16 l = __float2bfloat16(w - __bfloat162float(h));
        g_wimg[m][0][n * 136 + k] = h;
        g_wimg[m][1][n * 136 + k] = l;
    } else if (gid < 73728) {
        int idx = gid - 65536;
        int k = idx >> 7, n = idx & 127;
        float w = wre[k * 128 + n];
        __nv_bfloat16 h = __float2bfloat16(w);
        __nv_bfloat16 l = __float2bfloat16(w - __bfloat162float(h));
        g_wreimg[0][n * 72 + k] = h;
        g_wreimg[1][n * 72 + k] = l;
    } else if (gid < 90112) {
        int idx = gid - 73728;
        int hh = idx >> 11, r = idx & 2047;
        int n = r >> 4, k = r & 15;
        float w = wc[(hh * 16 + k) * 128 + n];
        __nv_bfloat16 h = __float2bfloat16(w);
        __nv_bfloat16 l = __float2bfloat16(w - __bfloat162float(h));
        g_wcimg[hh][0][n * 24 + k] = h;
        g_wcimg[hh][1][n * 24 + k] = l;
    }
}

// =============== node stage v4: 256 thr, 128-row tiles, M32xN64, single W buffer ===============
#define N4_BIAS 0
#define N4_AH   1024
#define N4_AL   (N4_AH + 34816)
#define N4_W    (N4_AL + 34816)
#define NODE4_SMEM (N4_W + 34816)   // 105472 -> 2 CTAs x 256 thr = 16 warps/SM

__device__ __forceinline__ void copy_w_one(char* smem, const __nv_bfloat16* src, int tid) {
    const uint4* s = (const uint4*)src;
    uint4* d = (uint4*)(smem + N4_W);
#pragma unroll
    for (int i = 0; i < 8; i++) d[tid + 256 * i] = s[tid + 256 * i];   // 32768B
    if (tid < 128) d[tid + 2048] = s[tid + 2048];                      // +2048B = 34816B
}
__device__ __forceinline__ void copy_wc2(char* smem, const __nv_bfloat16* src, int tid) {
    const uint4* s = (const uint4*)src;
    uint4* d = (uint4*)(smem + N4_W);
#pragma unroll
    for (int i = 0; i < 6; i++) d[tid + 256 * i] = s[tid + 256 * i];   // 24576B (2 heads)
}

__global__ void __launch_bounds__(256, 2) node_all(
    const float* __restrict__ H,
    const float* __restrict__ bq, const float* __restrict__ bk,
    const float* __restrict__ mb1, const float* __restrict__ mb2,
    float* __restrict__ Q, float* __restrict__ K, float* __restrict__ P, int nrows)
{
    extern __shared__ char smem[];
    uint32_t sb = smem_to_u32(smem);
    float* smb = (float*)(smem + N4_BIAS);
    int tid = threadIdx.x, wid = tid >> 5, lane = tid & 31;
    int role = blockIdx.x & 1;
    int tile = blockIdx.x >> 1;
    int row0 = tile * 128;
    int mrow = (wid & 3) * 32;    // M32 group within 128 rows
    int nh   = wid >> 2;          // N-half
    int g = lane >> 2, tig = lane & 3;

    if (role == 0) smb[tid] = (tid < 128) ? bq[tid] : bk[tid - 128];
    else           smb[tid] = (tid < 128) ? mb1[tid] : mb2[tid - 128];

    // A = h tile split (128 rows x 32 f4 = 4096 f4, 16 iters @256thr)
#pragma unroll
    for (int it = 0; it < 16; it++) {
        int idx = it * 256 + tid;
        int r = idx >> 5, c4 = (idx & 31) * 4;
        float4 x = make_float4(0.f, 0.f, 0.f, 0.f);
        if (row0 + r < nrows) x = *(const float4*)(H + (size_t)(row0 + r) * 128 + c4);
        uint32_t h0, l0, h1, l1;
        split2(x.x, x.y, h0, l0);
        split2(x.z, x.w, h1, l1);
        uint32_t o = (uint32_t)(r * 272 + c4 * 2);
        asm volatile("st.shared.v2.b32 [%0], {%1, %2};" :: "r"(sb + N4_AH + o), "r"(h0), "r"(h1));
        asm volatile("st.shared.v2.b32 [%0], {%1, %2};" :: "r"(sb + N4_AL + o), "r"(l0), "r"(l1));
    }

    uint32_t aH = a_lane_addr(sb + N4_AH, mrow, lane, 272);
    uint32_t aL = a_lane_addr(sb + N4_AL, mrow, lane, 272);
    uint32_t wB = b_lane_addr(sb + N4_W + nh * 17408, lane, 272);

    float acc0[8][4], acc1[8][4];
    int r0lo = row0 + mrow + g, r0hi = r0lo + 8;
    int r1lo = r0lo + 16,       r1hi = r0lo + 24;
    bool l0lo = r0lo < nrows, l0hi = r0hi < nrows;
    bool l1lo = r1lo < nrows, l1hi = r1hi < nrows;

#define ZERO_ACC() do { \
    _Pragma("unroll") for (int i = 0; i < 8; i++) { \
        acc0[i][0]=acc0[i][1]=acc0[i][2]=acc0[i][3]=0.f; \
        acc1[i][0]=acc1[i][1]=acc1[i][2]=acc1[i][3]=0.f; } } while (0)

#define GEMM3(WIMG) do { \
        copy_w_one(smem, &g_wimg[WIMG][0][0], tid); \
        __syncthreads(); \
        ZERO_ACC(); \
        warp_gemm_bh<8>(aH, aL, 272, wB, 272, acc0, acc1); \
        __syncthreads(); \
        copy_w_one(smem, &g_wimg[WIMG][1][0], tid); \
        __syncthreads(); \
        warp_gemm_al<8>(aH, 272, wB, 272, acc0, acc1); \
    } while (0)

#define STORE_OUT(DST, BOFF) do { \
    _Pragma("unroll") for (int nb = 0; nb < 8; nb++) { \
        int c = nh * 64 + nb * 8 + tig * 2; \
        float b0 = smb[(BOFF) + c], b1 = smb[(BOFF) + c + 1]; \
        if (l0lo) *(float2*)((DST) + (size_t)r0lo * 128 + c) = make_float2(acc0[nb][0] + b0, acc0[nb][1] + b1); \
        if (l0hi) *(float2*)((DST) + (size_t)r0hi * 128 + c) = make_float2(acc0[nb][2] + b0, acc0[nb][3] + b1); \
        if (l1lo) *(float2*)((DST) + (size_t)r1lo * 128 + c) = make_float2(acc1[nb][0] + b0, acc1[nb][1] + b1); \
        if (l1hi) *(float2*)((DST) + (size_t)r1hi * 128 + c) = make_float2(acc1[nb][2] + b0, acc1[nb][3] + b1); \
    } } while (0)

    if (role == 0) {
        GEMM3(0);                 // wq
        STORE_OUT(Q, 0);
        __syncthreads();
        GEMM3(1);                 // wk
        STORE_OUT(K, 128);
    } else {
        GEMM3(2);                 // mw1
        __syncthreads();
        // t1 = silu(..) split back into A
#pragma unroll
        for (int nb = 0; nb < 8; nb++) {
            int c = nh * 64 + nb * 8 + tig * 2;
            float b0 = smb[c], b1 = smb[c + 1];
            uint32_t hi, lo;
            split2(silu_f(acc0[nb][0] + b0), silu_f(acc0[nb][1] + b1), hi, lo);
            uint32_t o = (uint32_t)((mrow + g) * 272 + c * 2);
            asm volatile("st.shared.b32 [%0], %1;" :: "r"(sb + N4_AH + o), "r"(hi));
            asm volatile("st.shared.b32 [%0], %1;" :: "r"(sb + N4_AL + o), "r"(lo));
            split2(silu_f(acc0[nb][2] + b0), silu_f(acc0[nb][3] + b1), hi, lo);
            o = (uint32_t)((mrow + g + 8) * 272 + c * 2);
            asm volatile("st.shared.b32 [%0], %1;" :: "r"(sb + N4_AH + o), "r"(hi));
            asm volatile("st.shared.b32 [%0], %1;" :: "r"(sb + N4_AL + o), "r"(lo));
            split2(silu_f(acc1[nb][0] + b0), silu_f(acc1[nb][1] + b1), hi, lo);
            o = (uint32_t)((mrow + g + 16) * 272 + c * 2);
            asm volatile("st.shared.b32 [%0], %1;" :: "r"(sb + N4_AH + o), "r"(hi));
            asm volatile("st.shared.b32 [%0], %1;" :: "r"(sb + N4_AL + o), "r"(lo));
            split2(silu_f(acc1[nb][2] + b0), silu_f(acc1[nb][3] + b1), hi, lo);
            o = (uint32_t)((mrow + g + 24) * 272 + c * 2);
            asm volatile("st.shared.b32 [%0], %1;" :: "r"(sb + N4_AH + o), "r"(hi));
            asm volatile("st.shared.b32 [%0], %1;" :: "r"(sb + N4_AL + o), "r"(lo));
        }
        __syncthreads();
        GEMM3(3);                 // mw2
        __syncthreads();
        // v split back into A
#pragma unroll
        for (int nb = 0; nb < 8; nb++) {
            int c = nh * 64 + nb * 8 + tig * 2;
            float b0 = smb[128 + c], b1 = smb[128 + c + 1];
            uint32_t hi, lo;
            split2(acc0[nb][0] + b0, acc0[nb][1] + b1, hi, lo);
            uint32_t o = (uint32_t)((mrow + g) * 272 + c * 2);
            asm volatile("st.shared.b32 [%0], %1;" :: "r"(sb + N4_AH + o), "r"(hi));
            asm volatile("st.shared.b32 [%0], %1;" :: "r"(sb + N4_AL + o), "r"(lo));
            split2(acc0[nb][2] + b0, acc0[nb][3] + b1, hi, lo);
            o = (uint32_t)((mrow + g + 8) * 272 + c * 2);
            asm volatile("st.shared.b32 [%0], %1;" :: "r"(sb + N4_AH + o), "r"(hi));
            asm volatile("st.shared.b32 [%0], %1;" :: "r"(sb + N4_AL + o), "r"(lo));
            split2(acc1[nb][0] + b0, acc1[nb][1] + b1, hi, lo);
            o = (uint32_t)((mrow + g + 16) * 272 + c * 2);
            asm volatile("st.shared.b32 [%0], %1;" :: "r"(sb + N4_AH + o), "r"(hi));
            asm volatile("st.shared.b32 [%0], %1;" :: "r"(sb + N4_AL + o), "r"(lo));
            split2(acc1[nb][2] + b0, acc1[nb][3] + b1, hi, lo);
            o = (uint32_t)((mrow + g + 24) * 272 + c * 2);
            asm volatile("st.shared.b32 [%0], %1;" :: "r"(sb + N4_AH + o), "r"(hi));
            asm volatile("st.shared.b32 [%0], %1;" :: "r"(sb + N4_AL + o), "r"(lo));
        }
        __syncthreads();
        // P GEMMs: 2 heads per copy phase
#pragma unroll
        for (int ph = 0; ph < 4; ph++) {
            copy_wc2(smem, &g_wcimg[ph * 2][0][0], tid);
            __syncthreads();
#pragma unroll
            for (int hi2 = 0; hi2 < 2; hi2++) {
                int hh = ph * 2 + hi2;
                ZERO_ACC();
                warp_gemm_m2<1>(aH + hh * 32, aL + hh * 32, 272,
                                b_lane_addr(sb + N4_W + hi2 * 12288 + nh * 3072, lane, 48),
                                b_lane_addr(sb + N4_W + hi2 * 12288 + 6144 + nh * 3072, lane, 48), 48,
                                acc0, acc1);
#pragma unroll
                for (int nb = 0; nb < 8; nb++) {
                    int c = hh * 128 + nh * 64 + nb * 8 + tig * 2;
                    if (l0lo) *(float2*)(P + (size_t)r0lo * 1024 + c) = make_float2(acc0[nb][0], acc0[nb][1]);
                    if (l0hi) *(float2*)(P + (size_t)r0hi * 1024 + c) = make_float2(acc0[nb][2], acc0[nb][3]);
                    if (l1lo) *(float2*)(P + (size_t)r1lo * 1024 + c) = make_float2(acc1[nb][0], acc1[nb][1]);
                    if (l1hi) *(float2*)(P + (size_t)r1hi * 1024 + c) = make_float2(acc1[nb][2], acc1[nb][3]);
                }
            }
            __syncthreads();
        }
    }
#undef ZERO_ACC
#undef GEMM3
#undef STORE_OUT
}

// =============== edge logits v4 (unchanged) ===============
#define E4_BIAS 0
#define E4_TH   512
#define E4_TL   (E4_TH + 9216)
#define E4_WH   (E4_TL + 9216)
#define E4_WL   (E4_WH + 18432)
#define E4_RE   512
#define E4_IDX  50688
#define EDGE4_SMEM (E4_WL + 18432)     // 55808

__global__ void __launch_bounds__(256, 4) edge_logits_v4(
    const float* __restrict__ T, const int* __restrict__ EI, const float* __restrict__ BRE)
{
    extern __shared__ char smem[];
    uint32_t sb = smem_to_u32(smem);
    float* smb = (float*)(smem + E4_BIAS);
    float* sRe = (float*)(smem + E4_RE);
    int*   sIx = (int*)  (smem + E4_IDX);
    int tid = threadIdx.x, wid = tid >> 5, lane = tid & 31;
    int e0 = blockIdx.x * 64;
    int mrow = (wid & 3) * 16;
    int nh   = wid >> 2;
    int g = lane >> 2, tig = lane & 3;

    if (tid < 128) smb[tid] = BRE[tid];
    {
        const uint4* s = (const uint4*)(&g_wreimg[0][0]);
        uint4* d = (uint4*)(smem + E4_WH);
#pragma unroll
        for (int i = 0; i < 9; i++) d[tid + 256 * i] = s[tid + 256 * i];
    }
#pragma unroll
    for (int it = 0; it < 4; it++) {
        int idx = it * 256 + tid;
        int r = idx >> 4, c4 = (idx & 15) * 4;
        float4 x = *(const float4*)(T + (size_t)(e0 + r) * 64 + c4);
        uint32_t h0, l0, h1, l1;
        split2(x.x, x.y, h0, l0);
        split2(x.z, x.w, h1, l1);
        uint32_t o = (uint32_t)(r * 144 + c4 * 2);
        asm volatile("st.shared.v2.b32 [%0], {%1, %2};" :: "r"(sb + E4_TH + o), "r"(h0), "r"(h1));
        asm volatile("st.shared.v2.b32 [%0], {%1, %2};" :: "r"(sb + E4_TL + o), "r"(l0), "r"(l1));
    }
    __syncthreads();

    float acc[8][4];
#pragma unroll
    for (int i = 0; i < 8; i++) { acc[i][0] = acc[i][1] = acc[i][2] = acc[i][3] = 0.f; }
    warp_gemm_h<4>(a_lane_addr(sb + E4_TH, mrow, lane, 144), a_lane_addr(sb + E4_TL, mrow, lane, 144),
                   b_lane_addr(sb + E4_WH + nh * 9216, lane, 144),
                   b_lane_addr(sb + E4_WL + nh * 9216, lane, 144), 144, acc);
    __syncthreads();

    if (tid < 128) sIx[tid] = (tid < 64) ? EI[e0 + tid] : EI[NE + e0 + (tid - 64)];
#pragma unroll
    for (int nb = 0; nb < 8; nb++) {
        int c = nh * 64 + nb * 8 + tig * 2;
        float b0 = smb[c], b1 = smb[c + 1];
        *(float2*)(sRe + (mrow + g) * 132 + c)     = make_float2(silu_f(acc[nb][0] + b0), silu_f(acc[nb][1] + b1));
        *(float2*)(sRe + (mrow + g + 8) * 132 + c) = make_float2(silu_f(acc[nb][2] + b0), silu_f(acc[nb][3] + b1));
    }
    __syncthreads();

#pragma unroll
    for (int i0 = 0; i0 < 8; i0 += 4) {
        float4 q4[4], k4[4];
#pragma unroll
        for (int j = 0; j < 4; j++) {
            int el = wid * 8 + i0 + j;
            int nj = sIx[el];
            int ni = sIx[64 + el];
            q4[j] = *(const float4*)(g_q + (size_t)ni * 128 + lane * 4);
            k4[j] = *(const float4*)(g_k + (size_t)nj * 128 + lane * 4);
        }
#pragma unroll
        for (int j = 0; j < 4; j++) {
            int el = wid * 8 + i0 + j;
            float4 r4 = *(const float4*)(sRe + el * 132 + lane * 4);
            float p = q4[j].x * k4[j].x * r4.x + q4[j].y * k4[j].y * r4.y
                    + q4[j].z * k4[j].z * r4.z + q4[j].w * k4[j].w * r4.w;
            p += __shfl_xor_sync(0xffffffffu, p, 1);
            p += __shfl_xor_sync(0xffffffffu, p, 2);
            if ((lane & 3) == 0) g_a[(size_t)(e0 + el) * 8 + (lane >> 2)] = p;
        }
    }
}

// =============== CSR machinery (unchanged) ===============
__global__ void init_kernel() {
    int i = blockIdx.x * blockDim.x + threadIdx.x;
    if (i < NN) { g_cnt[i] = 0; g_cntI[i] = 0; }
}
__global__ void hist_kernel(const int* __restrict__ EI) {
    int e = blockIdx.x * blockDim.x + threadIdx.x;
    if (e < NE) {
        atomicAdd(&g_cnt[EI[e]], 1);
        atomicAdd(&g_cntI[EI[NE + e]], 1);
    }
}
__global__ void __launch_bounds__(SCH) scanA() {
    const int* cnt = blockIdx.y ? g_cntI : g_cnt;
    __shared__ int sm[SCH];
    int tid = threadIdx.x;
    int i = blockIdx.x * SCH + tid;
    sm[tid] = (i < NN) ? cnt[i] : 0;
    __syncthreads();
#pragma unroll
    for (int off = SCH / 2; off > 0; off >>= 1) {
        if (tid < off) sm[tid] += sm[tid + off];
        __syncthreads();
    }
    if (tid == 0) g_part[blockIdx.y][blockIdx.x] = sm[0];
}
__global__ void __launch_bounds__(256) scanB() {
    __shared__ int sm[2][128];
    int tid = threadIdx.x;
    int y = tid >> 7, x = tid & 127;
    sm[y][x] = (x < SNB) ? g_part[y][x] : 0;
    __syncthreads();
#pragma unroll
    for (int off = 1; off < 128; off <<= 1) {
        int v = (x >= off) ? sm[y][x - off] : 0;
        __syncthreads();
        sm[y][x] += v;
        __syncthreads();
    }
    if (x < SNB) g_pp[y][x] = sm[y][x] - g_part[y][x];
    if (x == SNB - 1) {
        if (y == 0) g_off[NN]  = sm[0][x];
        else        g_offI[NN] = sm[1][x];
    }
}
__global__ void __launch_bounds__(SCH) scanC() {
    int* cnt = blockIdx.y ? g_cntI : g_cnt;
    int* off = blockIdx.y ? g_offI : g_off;
    __shared__ int sm[SCH];
    int tid = threadIdx.x;
    int i = blockIdx.x * SCH + tid;
    int self = (i < NN) ? cnt[i] : 0;
    sm[tid] = self;
    __syncthreads();
#pragma unroll
    for (int o = 1; o < SCH; o <<= 1) {
        int v = (tid >= o) ? sm[tid - o] : 0;
        __syncthreads();
        sm[tid] += v;
        __syncthreads();
    }
    if (i < NN) {
        int pref = g_pp[blockIdx.y][blockIdx.x] + sm[tid] - self;
        off[i] = pref;
        cnt[i] = pref;
    }
}
__global__ void scatter_kernel(const int* __restrict__ EI) {
    int e = blockIdx.x * blockDim.x + threadIdx.x;
    if (e < NE) {
        int pj = atomicAdd(&g_cnt[EI[e]], 1);
        g_order[pj] = e;
        int pi = atomicAdd(&g_cntI[EI[NE + e]], 1);
        g_orderI[pi] = e;
    }
}

// =============== segment softmax (unchanged) ===============
__global__ void __launch_bounds__(256) segment_softmax() {
    int i = blockIdx.x * 8 + (threadIdx.x >> 5);
    int lane = threadIdx.x & 31;
    if (i >= NN) return;
    int s = g_offI[i];
    int d = g_offI[i + 1] - s;
    if (d == 0) return;
    int nv = d * 8;
    int iters = (nv + 31) >> 5;
    const int CAP = 8;
    float vals[CAP];

    float mx = -1e30f;
#pragma unroll
    for (int it = 0; it < CAP; it++) {
        if (it < iters) {
            int v = it * 32 + lane;
            float val = -1e30f;
            if (v < nv) val = g_a[(size_t)g_orderI[s + (v >> 3)] * 8 + (v & 7)];
            vals[it] = val;
            mx = fmaxf(mx, val);
        }
    }
    for (int it = CAP; it < iters; it++) {
        int v = it * 32 + lane;
        if (v < nv) mx = fmaxf(mx, g_a[(size_t)g_orderI[s + (v >> 3)] * 8 + (v & 7)]);
    }
    mx = fmaxf(mx, __shfl_xor_sync(0xffffffffu, mx, 16));
    mx = fmaxf(mx, __shfl_xor_sync(0xffffffffu, mx, 8));

    float sum = 0.f;
#pragma unroll
    for (int it = 0; it < CAP; it++) {
        if (it < iters) {
            int v = it * 32 + lane;
            float ex = 0.f;
            if (v < nv) ex = __expf(vals[it] - mx);
            vals[it] = ex;
            sum += ex;
        }
    }
    for (int it = CAP; it < iters; it++) {
        int v = it * 32 + lane;
        if (v < nv) sum += __expf(g_a[(size_t)g_orderI[s + (v >> 3)] * 8 + (v & 7)] - mx);
    }
    sum += __shfl_xor_sync(0xffffffffu, sum, 16);
    sum += __shfl_xor_sync(0xffffffffu, sum, 8);

    float scale = sqrtf((float)d) * 0.25f / sum;
#pragma unroll
    for (int it = 0; it < CAP; it++) {
        if (it < iters) {
            int v = it * 32 + lane;
            if (v < nv) g_a[(size_t)g_orderI[s + (v >> 3)] * 8 + (v & 7)] = vals[it] * scale;
        }
    }
    for (int it = CAP; it < iters; it++) {
        int v = it * 32 + lane;
        if (v < nv) {
            size_t idx = (size_t)g_orderI[s + (v >> 3)] * 8 + (v & 7);
            g_a[idx] = __expf(g_a[idx] - mx) * scale;
        }
    }
}

// =============== output (unchanged) ===============
__global__ void __launch_bounds__(256) edge_out_sorted(
    const float* __restrict__ BC, float* __restrict__ OUT)
{
    int j = blockIdx.x * 8 + (threadIdx.x >> 5);
    int lane = threadIdx.x & 31;
    if (j >= NN) return;
    int s = g_off[j], e_end = g_off[j + 1];
    if (s == e_end) return;

    const float* Pj = g_P + (size_t)j * 1024;
    float4 p[8];
#pragma unroll
    for (int h = 0; h < 8; h++)
        p[h] = *(const float4*)(Pj + h * 128 + lane * 4);
    float4 b4 = *(const float4*)(BC + lane * 4);

    for (int x = s; x < e_end; x++) {
        int e = g_order[x];
        float w = 0.f;
        if (lane < 8) w = g_a[(size_t)e * 8 + lane];

        float4 acc = b4;
#pragma unroll
        for (int h = 0; h < 8; h++) {
            float wh = __shfl_sync(0xffffffffu, w, h);
            acc.x = fmaf(wh, p[h].x, acc.x);
            acc.y = fmaf(wh, p[h].y, acc.y);
            acc.z = fmaf(wh, p[h].z, acc.z);
            acc.w = fmaf(wh, p[h].w, acc.w);
        }
        *(float4*)(OUT + (size_t)e * 128 + lane * 4) = acc;
    }
}

// =============== launch (node_all is launch #4 for ncu) ===============
extern "C" void kernel_launch(void* const* d_in, const int* in_sizes, int n_in,
                              void* d_out, int out_size)
{
    const float* h   = (const float*)d_in[0];
    const float* t   = (const float*)d_in[1];
    const int*   ei  = (const int*)  d_in[2];
    const float* wq  = (const float*)d_in[3];
    const float* bq  = (const float*)d_in[4];
    const float* wk  = (const float*)d_in[5];
    const float* bk  = (const float*)d_in[6];
    const float* wre = (const float*)d_in[7];
    const float* bre = (const float*)d_in[8];
    const float* mw1 = (const float*)d_in[9];
    const float* mb1 = (const float*)d_in[10];
    const float* mw2 = (const float*)d_in[11];
    const float* mb2 = (const float*)d_in[12];
    const float* wc  = (const float*)d_in[13];
    const float* bc  = (const float*)d_in[14];
    float* out = (float*)d_out;

    (void)in_sizes; (void)n_in; (void)out_size;

    cudaFuncSetAttribute(node_all,       cudaFuncAttributeMaxDynamicSharedMemorySize, NODE4_SMEM);
    cudaFuncSetAttribute(edge_logits_v4, cudaFuncAttributeMaxDynamicSharedMemorySize, EDGE4_SMEM);

    float *q_p, *k_p, *P_p;
    cudaGetSymbolAddress((void**)&q_p, g_q);
    cudaGetSymbolAddress((void**)&k_p, g_k);
    cudaGetSymbolAddress((void**)&P_p, g_P);

    int ntiles = (NN + 127) / 128;   // 391

    // 1: prep; 2: init; 3: hist; 4: node_all <-- ncu captures #4
    prep_all<<<352, 256>>>(wq, wk, mw1, mw2, wre, wc);
    init_kernel<<<(NN + 255) / 256, 256>>>();
    hist_kernel<<<(NE + 255) / 256, 256>>>(ei);
    node_all<<<ntiles * 2, 256, NODE4_SMEM>>>(h, bq, bk, mb1, mb2, q_p, k_p, P_p, NN);

    scanA<<<dim3(SNB, 2), SCH>>>();
    scanB<<<1, 256>>>();
    scanC<<<dim3(SNB, 2), SCH>>>();
    scatter_kernel<<<(NE + 255) / 256, 256>>>(ei);

    edge_logits_v4<<<NE / 64, 256, EDGE4_SMEM>>>(t, ei, bre);
    segment_softmax<<<(NN + 7) / 8, 256>>>();
    edge_out_sorted<<<(NN + 7) / 8, 256>>>(bc, out);
}

// round 17
// speedup vs baseline: 1.0156x; 1.0156x over previous
#include <cuda_runtime.h>
#include <cuda_bf16.h>
#include <math.h>
#include <cstdint>

#define NN 50000
#define NE 400000

// =============== mma.sync helpers ===============
__device__ __forceinline__ uint32_t smem_to_u32(const void* p) {
    uint32_t a;
    asm("{ .reg .u64 t; cvta.to.shared.u64 t, %1; cvt.u32.u64 %0, t; }" : "=r"(a) : "l"(p));
    return a;
}
__device__ __forceinline__ void ldsm_x4(uint32_t addr, uint32_t* r) {
    asm volatile("ldmatrix.sync.aligned.m8n8.x4.shared.b16 {%0,%1,%2,%3}, [%4];"
        : "=r"(r[0]), "=r"(r[1]), "=r"(r[2]), "=r"(r[3]) : "r"(addr));
}
__device__ __forceinline__ void mma_bf16(float* d, const uint32_t* a, const uint32_t* b) {
    asm volatile("mma.sync.aligned.m16n8k16.row.col.f32.bf16.bf16.f32 "
        "{%0,%1,%2,%3}, {%4,%5,%6,%7}, {%8,%9}, {%0,%1,%2,%3};"
        : "+f"(d[0]), "+f"(d[1]), "+f"(d[2]), "+f"(d[3])
        : "r"(a[0]), "r"(a[1]), "r"(a[2]), "r"(a[3]), "r"(b[0]), "r"(b[1]));
}
__device__ __forceinline__ uint32_t a_lane_addr(uint32_t base, int R, int lane, int stride) {
    int t = lane >> 3;
    int row = R + (lane & 7) + (t & 1) * 8;
    int k8  = (t >> 1) * 8;
    return base + row * stride + k8 * 2;
}
__device__ __forceinline__ uint32_t b_lane_addr(uint32_t base, int lane, int stride) {
    int t = lane >> 3;
    int n  = (lane & 7) + (t >> 1) * 8;
    int k8 = (t & 1) * 8;
    return base + n * stride + k8 * 2;
}
// half-width N=64 (4 n-pairs), M16, acc[8][4]  (edge_logits)
template<int KSTEPS>
__device__ __forceinline__ void warp_gemm_h(
    uint32_t aH, uint32_t aL, uint32_t bH, uint32_t bL, int bstride, float (*acc)[4])
{
#pragma unroll
    for (int ks = 0; ks < KSTEPS; ks++) {
        uint32_t rah[4], ral[4];
        ldsm_x4(aH + ks * 32, rah);
        ldsm_x4(aL + ks * 32, ral);
#pragma unroll
        for (int nbp = 0; nbp < 4; nbp++) {
            uint32_t bh[4], bl[4];
            ldsm_x4(bH + nbp * 16 * bstride + ks * 32, bh);
            ldsm_x4(bL + nbp * 16 * bstride + ks * 32, bl);
            mma_bf16(acc[2 * nbp],     rah, bh);
            mma_bf16(acc[2 * nbp],     rah, bl);
            mma_bf16(acc[2 * nbp],     ral, bh);
            mma_bf16(acc[2 * nbp + 1], rah, bh + 2);
            mma_bf16(acc[2 * nbp + 1], rah, bl + 2);
            mma_bf16(acc[2 * nbp + 1], ral, bh + 2);
        }
    }
}
// node phase 1: single B image, both A parts, 2 M-tiles
template<int KSTEPS>
__device__ __forceinline__ void warp_gemm_bh(
    uint32_t aH, uint32_t aL, int astride,
    uint32_t bB, int bstride,
    float (*acc0)[4], float (*acc1)[4])
{
#pragma unroll
    for (int ks = 0; ks < KSTEPS; ks++) {
        uint32_t rah0[4], ral0[4], rah1[4], ral1[4];
        ldsm_x4(aH + ks * 32, rah0);
        ldsm_x4(aL + ks * 32, ral0);
        ldsm_x4(aH + 16 * astride + ks * 32, rah1);
        ldsm_x4(aL + 16 * astride + ks * 32, ral1);
#pragma unroll
        for (int nbp = 0; nbp < 4; nbp++) {
            uint32_t bb[4];
            ldsm_x4(bB + nbp * 16 * bstride + ks * 32, bb);
            mma_bf16(acc0[2 * nbp],     rah0, bb);
            mma_bf16(acc0[2 * nbp],     ral0, bb);
            mma_bf16(acc0[2 * nbp + 1], rah0, bb + 2);
            mma_bf16(acc0[2 * nbp + 1], ral0, bb + 2);
            mma_bf16(acc1[2 * nbp],     rah1, bb);
            mma_bf16(acc1[2 * nbp],     ral1, bb);
            mma_bf16(acc1[2 * nbp + 1], rah1, bb + 2);
            mma_bf16(acc1[2 * nbp + 1], ral1, bb + 2);
        }
    }
}
// node phase 2: single B image, A_hi only, 2 M-tiles
template<int KSTEPS>
__device__ __forceinline__ void warp_gemm_al(
    uint32_t aH, int astride,
    uint32_t bB, int bstride,
    float (*acc0)[4], float (*acc1)[4])
{
#pragma unroll
    for (int ks = 0; ks < KSTEPS; ks++) {
        uint32_t rah0[4], rah1[4];
        ldsm_x4(aH + ks * 32, rah0);
        ldsm_x4(aH + 16 * astride + ks * 32, rah1);
#pragma unroll
        for (int nbp = 0; nbp < 4; nbp++) {
            uint32_t bb[4];
            ldsm_x4(bB + nbp * 16 * bstride + ks * 32, bb);
            mma_bf16(acc0[2 * nbp],     rah0, bb);
            mma_bf16(acc0[2 * nbp + 1], rah0, bb + 2);
            mma_bf16(acc1[2 * nbp],     rah1, bb);
            mma_bf16(acc1[2 * nbp + 1], rah1, bb + 2);
        }
    }
}
// M32 x N64 paired-B (wc P-GEMMs)
template<int KSTEPS>
__device__ __forceinline__ void warp_gemm_m2(
    uint32_t aH, uint32_t aL, int astride,
    uint32_t bH, uint32_t bL, int bstride,
    float (*acc0)[4], float (*acc1)[4])
{
#pragma unroll
    for (int ks = 0; ks < KSTEPS; ks++) {
        uint32_t rah0[4], ral0[4], rah1[4], ral1[4];
        ldsm_x4(aH + ks * 32, rah0);
        ldsm_x4(aL + ks * 32, ral0);
        ldsm_x4(aH + 16 * astride + ks * 32, rah1);
        ldsm_x4(aL + 16 * astride + ks * 32, ral1);
#pragma unroll
        for (int nbp = 0; nbp < 4; nbp++) {
            uint32_t bh[4], bl[4];
            ldsm_x4(bH + nbp * 16 * bstride + ks * 32, bh);
            ldsm_x4(bL + nbp * 16 * bstride + ks * 32, bl);
            mma_bf16(acc0[2 * nbp],     rah0, bh);
            mma_bf16(acc0[2 * nbp],     rah0, bl);
            mma_bf16(acc0[2 * nbp],     ral0, bh);
            mma_bf16(acc0[2 * nbp + 1], rah0, bh + 2);
            mma_bf16(acc0[2 * nbp + 1], rah0, bl + 2);
            mma_bf16(acc0[2 * nbp + 1], ral0, bh + 2);
            mma_bf16(acc1[2 * nbp],     rah1, bh);
            mma_bf16(acc1[2 * nbp],     rah1, bl);
            mma_bf16(acc1[2 * nbp],     ral1, bh);
            mma_bf16(acc1[2 * nbp + 1], rah1, bh + 2);
            mma_bf16(acc1[2 * nbp + 1], rah1, bl + 2);
            mma_bf16(acc1[2 * nbp + 1], ral1, bh + 2);
        }
    }
}

__device__ __forceinline__ float silu_f(float x) { return x / (1.0f + __expf(-x)); }
__device__ __forceinline__ void split2(float x0, float x1, uint32_t& hi, uint32_t& lo) {
    __nv_bfloat16 h0 = __float2bfloat16(x0), h1 = __float2bfloat16(x1);
    __nv_bfloat16 l0 = __float2bfloat16(x0 - __bfloat162float(h0));
    __nv_bfloat16 l1 = __float2bfloat16(x1 - __bfloat162float(h1));
    __nv_bfloat162 H; H.x = h0; H.y = h1;
    __nv_bfloat162 L; L.x = l0; L.y = l1;
    hi = *(uint32_t*)&H; lo = *(uint32_t*)&L;
}

// =============== scratch globals ===============
__device__ __align__(16) float g_q [NN * 128];
__device__ __align__(16) float g_k [NN * 128];
__device__ __align__(16) float g_P [(size_t)NN * 1024];
__device__ __align__(16) float g_a [(size_t)NE * 8];
__device__ int g_cnt  [NN];
__device__ int g_cntI [NN];
__device__ int g_off  [NN + 1];
__device__ int g_offI [NN + 1];
__device__ int g_order [NE];
__device__ int g_orderI[NE];
#define SCH 512
#define SNB ((NN + SCH - 1) / SCH)
__device__ int g_part[2][SNB];
__device__ int g_pp  [2][SNB];
__device__ __align__(16) __nv_bfloat16 g_wimg [4][2][128 * 136];
__device__ __align__(16) __nv_bfloat16 g_wreimg[2][128 * 72];
__device__ __align__(16) __nv_bfloat16 g_wcimg [8][2][128 * 24];

// =============== merged weight prep + counter init ===============
__global__ void prep_all(const float* __restrict__ wq, const float* __restrict__ wk,
                         const float* __restrict__ mw1, const float* __restrict__ mw2,
                         const float* __restrict__ wre, const float* __restrict__ wc) {
    int gid = blockIdx.x * blockDim.x + threadIdx.x;
    if (gid < NN) { g_cnt[gid] = 0; g_cntI[gid] = 0; }   // fold init here
    if (gid < 65536) {
        int m = gid >> 14, idx = gid & 16383;
        const float* W = (m == 0) ? wq : (m == 1) ? wk : (m == 2) ? mw1 : mw2;
        int k = idx >> 7, n = idx & 127;
        float w = W[k * 128 + n];
        __nv_bfloat16 h = __float2bfloat16(w);
        __nv_bfloat16 l = __float2bfloat16(w - __bfloat162float(h));
        g_wimg[m][0][n * 136 + k] = h;
        g_wimg[m][1][n * 136 + k] = l;
    } else if (gid < 73728) {
        int idx = gid - 65536;
        int k = idx >> 7, n = idx & 127;
        float w = wre[k * 128 + n];
        __nv_bfloat16 h = __float2bfloat16(w);
        __nv_bfloat16 l = __float2bfloat16(w - __bfloat162float(h));
        g_wreimg[0][n * 72 + k] = h;
        g_wreimg[1][n * 72 + k] = l;
    } else if (gid < 90112) {
        int idx = gid - 73728;
        int hh = idx >> 11, r = idx & 2047;
        int n = r >> 4, k = r & 15;
        float w = wc[(hh * 16 + k) * 128 + n];
        __nv_bfloat16 h = __float2bfloat16(w);
        __nv_bfloat16 l = __float2bfloat16(w - __bfloat162float(h));
        g_wcimg[hh][0][n * 24 + k] = h;
        g_wcimg[hh][1][n * 24 + k] = l;
    }
}

// =============== node stage (R15 best: 128 thr, 64-row tiles, single W buffer, 3 CTAs/SM) ===============
#define N3_BIAS 0
#define N3_AH   1024
#define N3_AL   (N3_AH + 17408)
#define N3_W    (N3_AL + 17408)
#define NODE3_SMEM (N3_W + 34816)   // 70656

__device__ __forceinline__ void copy_w_one(char* smem, const __nv_bfloat16* src, int tid) {
    const uint4* s = (const uint4*)src;
    uint4* d = (uint4*)(smem + N3_W);
#pragma unroll
    for (int i = 0; i < 17; i++) d[tid + 128 * i] = s[tid + 128 * i];
}
__device__ __forceinline__ void copy_wc2(char* smem, const __nv_bfloat16* src, int tid) {
    const uint4* s = (const uint4*)src;
    uint4* d = (uint4*)(smem + N3_W);
#pragma unroll
    for (int i = 0; i < 12; i++) d[tid + 128 * i] = s[tid + 128 * i];
}

__global__ void __launch_bounds__(128, 3) node_all(
    const float* __restrict__ H,
    const float* __restrict__ bq, const float* __restrict__ bk,
    const float* __restrict__ mb1, const float* __restrict__ mb2,
    float* __restrict__ Q, float* __restrict__ K, float* __restrict__ P, int nrows)
{
    extern __shared__ char smem[];
    uint32_t sb = smem_to_u32(smem);
    float* smb = (float*)(smem + N3_BIAS);
    int tid = threadIdx.x, wid = tid >> 5, lane = tid & 31;
    int role = blockIdx.x & 1;
    int tile = blockIdx.x >> 1;
    int row0 = tile * 64;
    int mrow = (wid & 1) * 32;
    int nh   = wid >> 1;
    int g = lane >> 2, tig = lane & 3;

    if (role == 0) { smb[tid] = bq[tid]; smb[128 + tid] = bk[tid]; }
    else           { smb[tid] = mb1[tid]; smb[128 + tid] = mb2[tid]; }

#pragma unroll
    for (int it = 0; it < 16; it++) {
        int idx = it * 128 + tid;
        int r = idx >> 5, c4 = (idx & 31) * 4;
        float4 x = make_float4(0.f, 0.f, 0.f, 0.f);
        if (row0 + r < nrows) x = *(const float4*)(H + (size_t)(row0 + r) * 128 + c4);
        uint32_t h0, l0, h1, l1;
        split2(x.x, x.y, h0, l0);
        split2(x.z, x.w, h1, l1);
        uint32_t o = (uint32_t)(r * 272 + c4 * 2);
        asm volatile("st.shared.v2.b32 [%0], {%1, %2};" :: "r"(sb + N3_AH + o), "r"(h0), "r"(h1));
        asm volatile("st.shared.v2.b32 [%0], {%1, %2};" :: "r"(sb + N3_AL + o), "r"(l0), "r"(l1));
    }

    uint32_t aH = a_lane_addr(sb + N3_AH, mrow, lane, 272);
    uint32_t aL = a_lane_addr(sb + N3_AL, mrow, lane, 272);
    uint32_t wB = b_lane_addr(sb + N3_W + nh * 17408, lane, 272);

    float acc0[8][4], acc1[8][4];
    int r0lo = row0 + mrow + g, r0hi = r0lo + 8;
    int r1lo = r0lo + 16,       r1hi = r0lo + 24;
    bool l0lo = r0lo < nrows, l0hi = r0hi < nrows;
    bool l1lo = r1lo < nrows, l1hi = r1hi < nrows;

#define ZERO_ACC() do { \
    _Pragma("unroll") for (int i = 0; i < 8; i++) { \
        acc0[i][0]=acc0[i][1]=acc0[i][2]=acc0[i][3]=0.f; \
        acc1[i][0]=acc1[i][1]=acc1[i][2]=acc1[i][3]=0.f; } } while (0)

#define GEMM3(WIMG) do { \
        copy_w_one(smem, &g_wimg[WIMG][0][0], tid); \
        __syncthreads(); \
        ZERO_ACC(); \
        warp_gemm_bh<8>(aH, aL, 272, wB, 272, acc0, acc1); \
        __syncthreads(); \
        copy_w_one(smem, &g_wimg[WIMG][1][0], tid); \
        __syncthreads(); \
        warp_gemm_al<8>(aH, 272, wB, 272, acc0, acc1); \
    } while (0)

#define STORE_OUT(DST, BOFF) do { \
    _Pragma("unroll") for (int nb = 0; nb < 8; nb++) { \
        int c = nh * 64 + nb * 8 + tig * 2; \
        float b0 = smb[(BOFF) + c], b1 = smb[(BOFF) + c + 1]; \
        if (l0lo) *(float2*)((DST) + (size_t)r0lo * 128 + c) = make_float2(acc0[nb][0] + b0, acc0[nb][1] + b1); \
        if (l0hi) *(float2*)((DST) + (size_t)r0hi * 128 + c) = make_float2(acc0[nb][2] + b0, acc0[nb][3] + b1); \
        if (l1lo) *(float2*)((DST) + (size_t)r1lo * 128 + c) = make_float2(acc1[nb][0] + b0, acc1[nb][1] + b1); \
        if (l1hi) *(float2*)((DST) + (size_t)r1hi * 128 + c) = make_float2(acc1[nb][2] + b0, acc1[nb][3] + b1); \
    } } while (0)

    if (role == 0) {
        GEMM3(0);
        STORE_OUT(Q, 0);
        __syncthreads();
        GEMM3(1);
        STORE_OUT(K, 128);
    } else {
        GEMM3(2);
        __syncthreads();
#pragma unroll
        for (int nb = 0; nb < 8; nb++) {
            int c = nh * 64 + nb * 8 + tig * 2;
            float b0 = smb[c], b1 = smb[c + 1];
            uint32_t hi, lo;
            split2(silu_f(acc0[nb][0] + b0), silu_f(acc0[nb][1] + b1), hi, lo);
            uint32_t o = (uint32_t)((mrow + g) * 272 + c * 2);
            asm volatile("st.shared.b32 [%0], %1;" :: "r"(sb + N3_AH + o), "r"(hi));
            asm volatile("st.shared.b32 [%0], %1;" :: "r"(sb + N3_AL + o), "r"(lo));
            split2(silu_f(acc0[nb][2] + b0), silu_f(acc0[nb][3] + b1), hi, lo);
            o = (uint32_t)((mrow + g + 8) * 272 + c * 2);
            asm volatile("st.shared.b32 [%0], %1;" :: "r"(sb + N3_AH + o), "r"(hi));
            asm volatile("st.shared.b32 [%0], %1;" :: "r"(sb + N3_AL + o), "r"(lo));
            split2(silu_f(acc1[nb][0] + b0), silu_f(acc1[nb][1] + b1), hi, lo);
            o = (uint32_t)((mrow + g + 16) * 272 + c * 2);
            asm volatile("st.shared.b32 [%0], %1;" :: "r"(sb + N3_AH + o), "r"(hi));
            asm volatile("st.shared.b32 [%0], %1;" :: "r"(sb + N3_AL + o), "r"(lo));
            split2(silu_f(acc1[nb][2] + b0), silu_f(acc1[nb][3] + b1), hi, lo);
            o = (uint32_t)((mrow + g + 24) * 272 + c * 2);
            asm volatile("st.shared.b32 [%0], %1;" :: "r"(sb + N3_AH + o), "r"(hi));
            asm volatile("st.shared.b32 [%0], %1;" :: "r"(sb + N3_AL + o), "r"(lo));
        }
        __syncthreads();
        GEMM3(3);
        __syncthreads();
#pragma unroll
        for (int nb = 0; nb < 8; nb++) {
            int c = nh * 64 + nb * 8 + tig * 2;
            float b0 = smb[128 + c], b1 = smb[128 + c + 1];
            uint32_t hi, lo;
            split2(acc0[nb][0] + b0, acc0[nb][1] + b1, hi, lo);
            uint32_t o = (uint32_t)((mrow + g) * 272 + c * 2);
            asm volatile("st.shared.b32 [%0], %1;" :: "r"(sb + N3_AH + o), "r"(hi));
            asm volatile("st.shared.b32 [%0], %1;" :: "r"(sb + N3_AL + o), "r"(lo));
            split2(acc0[nb][2] + b0, acc0[nb][3] + b1, hi, lo);
            o = (uint32_t)((mrow + g + 8) * 272 + c * 2);
            asm volatile("st.shared.b32 [%0], %1;" :: "r"(sb + N3_AH + o), "r"(hi));
            asm volatile("st.shared.b32 [%0], %1;" :: "r"(sb + N3_AL + o), "r"(lo));
            split2(acc1[nb][0] + b0, acc1[nb][1] + b1, hi, lo);
            o = (uint32_t)((mrow + g + 16) * 272 + c * 2);
            asm volatile("st.shared.b32 [%0], %1;" :: "r"(sb + N3_AH + o), "r"(hi));
            asm volatile("st.shared.b32 [%0], %1;" :: "r"(sb + N3_AL + o), "r"(lo));
            split2(acc1[nb][2] + b0, acc1[nb][3] + b1, hi, lo);
            o = (uint32_t)((mrow + g + 24) * 272 + c * 2);
            asm volatile("st.shared.b32 [%0], %1;" :: "r"(sb + N3_AH + o), "r"(hi));
            asm volatile("st.shared.b32 [%0], %1;" :: "r"(sb + N3_AL + o), "r"(lo));
        }
        __syncthreads();
#pragma unroll
        for (int ph = 0; ph < 4; ph++) {
            copy_wc2(smem, &g_wcimg[ph * 2][0][0], tid);
            __syncthreads();
#pragma unroll
            for (int hi2 = 0; hi2 < 2; hi2++) {
                int hh = ph * 2 + hi2;
                ZERO_ACC();
                warp_gemm_m2<1>(aH + hh * 32, aL + hh * 32, 272,
                                b_lane_addr(sb + N3_W + hi2 * 12288 + nh * 3072, lane, 48),
                                b_lane_addr(sb + N3_W + hi2 * 12288 + 6144 + nh * 3072, lane, 48), 48,
                                acc0, acc1);
#pragma unroll
                for (int nb = 0; nb < 8; nb++) {
                    int c = hh * 128 + nh * 64 + nb * 8 + tig * 2;
                    if (l0lo) *(float2*)(P + (size_t)r0lo * 1024 + c) = make_float2(acc0[nb][0], acc0[nb][1]);
                    if (l0hi) *(float2*)(P + (size_t)r0hi * 1024 + c) = make_float2(acc0[nb][2], acc0[nb][3]);
                    if (l1lo) *(float2*)(P + (size_t)r1lo * 1024 + c) = make_float2(acc1[nb][0], acc1[nb][1]);
                    if (l1hi) *(float2*)(P + (size_t)r1hi * 1024 + c) = make_float2(acc1[nb][2], acc1[nb][3]);
                }
            }
            __syncthreads();
        }
    }
#undef ZERO_ACC
#undef GEMM3
#undef STORE_OUT
}

// =============== edge logits v4 (unchanged) ===============
#define E4_BIAS 0
#define E4_TH   512
#define E4_TL   (E4_TH + 9216)
#define E4_WH   (E4_TL + 9216)
#define E4_WL   (E4_WH + 18432)
#define E4_RE   512
#define E4_IDX  50688
#define EDGE4_SMEM (E4_WL + 18432)     // 55808

__global__ void __launch_bounds__(256, 4) edge_logits_v4(
    const float* __restrict__ T, const int* __restrict__ EI, const float* __restrict__ BRE)
{
    extern __shared__ char smem[];
    uint32_t sb = smem_to_u32(smem);
    float* smb = (float*)(smem + E4_BIAS);
    float* sRe = (float*)(smem + E4_RE);
    int*   sIx = (int*)  (smem + E4_IDX);
    int tid = threadIdx.x, wid = tid >> 5, lane = tid & 31;
    int e0 = blockIdx.x * 64;
    int mrow = (wid & 3) * 16;
    int nh   = wid >> 2;
    int g = lane >> 2, tig = lane & 3;

    if (tid < 128) smb[tid] = BRE[tid];
    {
        const uint4* s = (const uint4*)(&g_wreimg[0][0]);
        uint4* d = (uint4*)(smem + E4_WH);
#pragma unroll
        for (int i = 0; i < 9; i++) d[tid + 256 * i] = s[tid + 256 * i];
    }
#pragma unroll
    for (int it = 0; it < 4; it++) {
        int idx = it * 256 + tid;
        int r = idx >> 4, c4 = (idx & 15) * 4;
        float4 x = *(const float4*)(T + (size_t)(e0 + r) * 64 + c4);
        uint32_t h0, l0, h1, l1;
        split2(x.x, x.y, h0, l0);
        split2(x.z, x.w, h1, l1);
        uint32_t o = (uint32_t)(r * 144 + c4 * 2);
        asm volatile("st.shared.v2.b32 [%0], {%1, %2};" :: "r"(sb + E4_TH + o), "r"(h0), "r"(h1));
        asm volatile("st.shared.v2.b32 [%0], {%1, %2};" :: "r"(sb + E4_TL + o), "r"(l0), "r"(l1));
    }
    __syncthreads();

    float acc[8][4];
#pragma unroll
    for (int i = 0; i < 8; i++) { acc[i][0] = acc[i][1] = acc[i][2] = acc[i][3] = 0.f; }
    warp_gemm_h<4>(a_lane_addr(sb + E4_TH, mrow, lane, 144), a_lane_addr(sb + E4_TL, mrow, lane, 144),
                   b_lane_addr(sb + E4_WH + nh * 9216, lane, 144),
                   b_lane_addr(sb + E4_WL + nh * 9216, lane, 144), 144, acc);
    __syncthreads();

    if (tid < 128) sIx[tid] = (tid < 64) ? EI[e0 + tid] : EI[NE + e0 + (tid - 64)];
#pragma unroll
    for (int nb = 0; nb < 8; nb++) {
        int c = nh * 64 + nb * 8 + tig * 2;
        float b0 = smb[c], b1 = smb[c + 1];
        *(float2*)(sRe + (mrow + g) * 132 + c)     = make_float2(silu_f(acc[nb][0] + b0), silu_f(acc[nb][1] + b1));
        *(float2*)(sRe + (mrow + g + 8) * 132 + c) = make_float2(silu_f(acc[nb][2] + b0), silu_f(acc[nb][3] + b1));
    }
    __syncthreads();

#pragma unroll
    for (int i0 = 0; i0 < 8; i0 += 4) {
        float4 q4[4], k4[4];
#pragma unroll
        for (int j = 0; j < 4; j++) {
            int el = wid * 8 + i0 + j;
            int nj = sIx[el];
            int ni = sIx[64 + el];
            q4[j] = *(const float4*)(g_q + (size_t)ni * 128 + lane * 4);
            k4[j] = *(const float4*)(g_k + (size_t)nj * 128 + lane * 4);
        }
#pragma unroll
        for (int j = 0; j < 4; j++) {
            int el = wid * 8 + i0 + j;
            float4 r4 = *(const float4*)(sRe + el * 132 + lane * 4);
            float p = q4[j].x * k4[j].x * r4.x + q4[j].y * k4[j].y * r4.y
                    + q4[j].z * k4[j].z * r4.z + q4[j].w * k4[j].w * r4.w;
            p += __shfl_xor_sync(0xffffffffu, p, 1);
            p += __shfl_xor_sync(0xffffffffu, p, 2);
            if ((lane & 3) == 0) g_a[(size_t)(e0 + el) * 8 + (lane >> 2)] = p;
        }
    }
}

// =============== CSR machinery ===============
__global__ void hist_kernel(const int* __restrict__ EI) {
    int e = blockIdx.x * blockDim.x + threadIdx.x;
    if (e < NE) {
        atomicAdd(&g_cnt[EI[e]], 1);
        atomicAdd(&g_cntI[EI[NE + e]], 1);
    }
}
__global__ void __launch_bounds__(SCH) scanA() {
    const int* cnt = blockIdx.y ? g_cntI : g_cnt;
    __shared__ int sm[SCH];
    int tid = threadIdx.x;
    int i = blockIdx.x * SCH + tid;
    sm[tid] = (i < NN) ? cnt[i] : 0;
    __syncthreads();
#pragma unroll
    for (int off = SCH / 2; off > 0; off >>= 1) {
        if (tid < off) sm[tid] += sm[tid + off];
        __syncthreads();
    }
    if (tid == 0) g_part[blockIdx.y][blockIdx.x] = sm[0];
}
__global__ void __launch_bounds__(256) scanB() {
    __shared__ int sm[2][128];
    int tid = threadIdx.x;
    int y = tid >> 7, x = tid & 127;
    sm[y][x] = (x < SNB) ? g_part[y][x] : 0;
    __syncthreads();
#pragma unroll
    for (int off = 1; off < 128; off <<= 1) {
        int v = (x >= off) ? sm[y][x - off] : 0;
        __syncthreads();
        sm[y][x] += v;
        __syncthreads();
    }
    if (x < SNB) g_pp[y][x] = sm[y][x] - g_part[y][x];
    if (x == SNB - 1) {
        if (y == 0) g_off[NN]  = sm[0][x];
        else        g_offI[NN] = sm[1][x];
    }
}
__global__ void __launch_bounds__(SCH) scanC() {
    int* cnt = blockIdx.y ? g_cntI : g_cnt;
    int* off = blockIdx.y ? g_offI : g_off;
    __shared__ int sm[SCH];
    int tid = threadIdx.x;
    int i = blockIdx.x * SCH + tid;
    int self = (i < NN) ? cnt[i] : 0;
    sm[tid] = self;
    __syncthreads();
#pragma unroll
    for (int o = 1; o < SCH; o <<= 1) {
        int v = (tid >= o) ? sm[tid - o] : 0;
        __syncthreads();
        sm[tid] += v;
        __syncthreads();
    }
    if (i < NN) {
        int pref = g_pp[blockIdx.y][blockIdx.x] + sm[tid] - self;
        off[i] = pref;
        cnt[i] = pref;
    }
}
__global__ void scatter_kernel(const int* __restrict__ EI) {
    int e = blockIdx.x * blockDim.x + threadIdx.x;
    if (e < NE) {
        int pj = atomicAdd(&g_cnt[EI[e]], 1);
        g_order[pj] = e;
        int pi = atomicAdd(&g_cntI[EI[NE + e]], 1);
        g_orderI[pi] = e;
    }
}

// =============== segment softmax (unchanged) ===============
__global__ void __launch_bounds__(256) segment_softmax() {
    int i = blockIdx.x * 8 + (threadIdx.x >> 5);
    int lane = threadIdx.x & 31;
    if (i >= NN) return;
    int s = g_offI[i];
    int d = g_offI[i + 1] - s;
    if (d == 0) return;
    int nv = d * 8;
    int iters = (nv + 31) >> 5;
    const int CAP = 8;
    float vals[CAP];

    float mx = -1e30f;
#pragma unroll
    for (int it = 0; it < CAP; it++) {
        if (it < iters) {
            int v = it * 32 + lane;
            float val = -1e30f;
            if (v < nv) val = g_a[(size_t)g_orderI[s + (v >> 3)] * 8 + (v & 7)];
            vals[it] = val;
            mx = fmaxf(mx, val);
        }
    }
    for (int it = CAP; it < iters; it++) {
        int v = it * 32 + lane;
        if (v < nv) mx = fmaxf(mx, g_a[(size_t)g_orderI[s + (v >> 3)] * 8 + (v & 7)]);
    }
    mx = fmaxf(mx, __shfl_xor_sync(0xffffffffu, mx, 16));
    mx = fmaxf(mx, __shfl_xor_sync(0xffffffffu, mx, 8));

    float sum = 0.f;
#pragma unroll
    for (int it = 0; it < CAP; it++) {
        if (it < iters) {
            int v = it * 32 + lane;
            float ex = 0.f;
            if (v < nv) ex = __expf(vals[it] - mx);
            vals[it] = ex;
            sum += ex;
        }
    }
    for (int it = CAP; it < iters; it++) {
        int v = it * 32 + lane;
        if (v < nv) sum += __expf(g_a[(size_t)g_orderI[s + (v >> 3)] * 8 + (v & 7)] - mx);
    }
    sum += __shfl_xor_sync(0xffffffffu, sum, 16);
    sum += __shfl_xor_sync(0xffffffffu, sum, 8);

    float scale = sqrtf((float)d) * 0.25f / sum;
#pragma unroll
    for (int it = 0; it < CAP; it++) {
        if (it < iters) {
            int v = it * 32 + lane;
            if (v < nv) g_a[(size_t)g_orderI[s + (v >> 3)] * 8 + (v & 7)] = vals[it] * scale;
        }
    }
    for (int it = CAP; it < iters; it++) {
        int v = it * 32 + lane;
        if (v < nv) {
            size_t idx = (size_t)g_orderI[s + (v >> 3)] * 8 + (v & 7);
            g_a[idx] = __expf(g_a[idx] - mx) * scale;
        }
    }
}

// =============== output (unchanged) ===============
__global__ void __launch_bounds__(256) edge_out_sorted(
    const float* __restrict__ BC, float* __restrict__ OUT)
{
    int j = blockIdx.x * 8 + (threadIdx.x >> 5);
    int lane = threadIdx.x & 31;
    if (j >= NN) return;
    int s = g_off[j], e_end = g_off[j + 1];
    if (s == e_end) return;

    const float* Pj = g_P + (size_t)j * 1024;
    float4 p[8];
#pragma unroll
    for (int h = 0; h < 8; h++)
        p[h] = *(const float4*)(Pj + h * 128 + lane * 4);
    float4 b4 = *(const float4*)(BC + lane * 4);

    for (int x = s; x < e_end; x++) {
        int e = g_order[x];
        float w = 0.f;
        if (lane < 8) w = g_a[(size_t)e * 8 + lane];

        float4 acc = b4;
#pragma unroll
        for (int h = 0; h < 8; h++) {
            float wh = __shfl_sync(0xffffffffu, w, h);
            acc.x = fmaf(wh, p[h].x, acc.x);
            acc.y = fmaf(wh, p[h].y, acc.y);
            acc.z = fmaf(wh, p[h].z, acc.z);
            acc.w = fmaf(wh, p[h].w, acc.w);
        }
        *(float4*)(OUT + (size_t)e * 128 + lane * 4) = acc;
    }
}

// =============== launch ===============
extern "C" void kernel_launch(void* const* d_in, const int* in_sizes, int n_in,
                              void* d_out, int out_size)
{
    const float* h   = (const float*)d_in[0];
    const float* t   = (const float*)d_in[1];
    const int*   ei  = (const int*)  d_in[2];
    const float* wq  = (const float*)d_in[3];
    const float* bq  = (const float*)d_in[4];
    const float* wk  = (const float*)d_in[5];
    const float* bk  = (const float*)d_in[6];
    const float* wre = (const float*)d_in[7];
    const float* bre = (const float*)d_in[8];
    const float* mw1 = (const float*)d_in[9];
    const float* mb1 = (const float*)d_in[10];
    const float* mw2 = (const float*)d_in[11];
    const float* mb2 = (const float*)d_in[12];
    const float* wc  = (const float*)d_in[13];
    const float* bc  = (const float*)d_in[14];
    float* out = (float*)d_out;

    (void)in_sizes; (void)n_in; (void)out_size;

    cudaFuncSetAttribute(node_all,       cudaFuncAttributeMaxDynamicSharedMemorySize, NODE3_SMEM);
    cudaFuncSetAttribute(edge_logits_v4, cudaFuncAttributeMaxDynamicSharedMemorySize, EDGE4_SMEM);

    float *q_p, *k_p, *P_p;
    cudaGetSymbolAddress((void**)&q_p, g_q);
    cudaGetSymbolAddress((void**)&k_p, g_k);
    cudaGetSymbolAddress((void**)&P_p, g_P);

    int ntiles = (NN + 63) / 64;   // 782

    // 1: prep(+init); 2: hist; 3: scanA; 4: node_all <-- ncu captures #4
    prep_all<<<352, 256>>>(wq, wk, mw1, mw2, wre, wc);
    hist_kernel<<<(NE + 255) / 256, 256>>>(ei);
    scanA<<<dim3(SNB, 2), SCH>>>();
    node_all<<<ntiles * 2, 128, NODE3_SMEM>>>(h, bq, bk, mb1, mb2, q_p, k_p, P_p, NN);

    scanB<<<1, 256>>>();
    scanC<<<dim3(SNB, 2), SCH>>>();
    scatter_kernel<<<(NE + 255) / 256, 256>>>(ei);

    edge_logits_v4<<<NE / 64, 256, EDGE4_SMEM>>>(t, ei, bre);
    segment_softmax<<<(NN + 7) / 8, 256>>>();
    edge_out_sorted<<<(NN + 7) / 8, 256>>>(bc, out);
}